// round 1
// baseline (speedup 1.0000x reference)
#include <cuda_runtime.h>
#include <math.h>

#define B_  4
#define C_  64
#define T_  4096
#define NH  8
#define DH  8
#define KP  1024
#define J3  192

// Scratch (device globals; no allocation allowed)
__device__ float g_qkv[B_ * J3 * T_];        // [b][j][t]   j = d*24 + mat*8 + h
__device__ float g_proj[2 * B_ * C_ * KP];   // [mat][b][h*8+d][kk]
__device__ float g_att[B_ * C_ * T_];        // [b][h*8+d][t]

// ---------------------------------------------------------------------------
__global__ void zero_proj_kernel() {
    int i = blockIdx.x * blockDim.x + threadIdx.x;   // 131072 float4 total
    ((float4*)g_proj)[i] = make_float4(0.f, 0.f, 0.f, 0.f);
}

// ---------------------------------------------------------------------------
// qkv[b, j, t] = sum_c x[b, c, t] * Wqkv[c, j]
// tile: 64 j x 64 t, K=64. grid = b * 3(jg) * 64(ttile)
__global__ void qkv_kernel(const float* __restrict__ x,
                           const float* __restrict__ Wqkv) {
    __shared__ __align__(16) float ws[64 * 64];   // [c][j]
    __shared__ __align__(16) float xs[64 * 64];   // [c][t]
    int id = blockIdx.x;
    int ttile = id & 63; id >>= 6;
    int jg = id % 3;
    int b  = id / 3;
    int t0 = ttile * 64;
    int tid = threadIdx.x;

#pragma unroll
    for (int k = 0; k < 4; k++) {
        int ii = tid + k * 256;           // float4 index 0..1023
        int c = ii >> 4, j4 = ii & 15;
        ((float4*)ws)[ii] = *(const float4*)&Wqkv[c * J3 + jg * 64 + j4 * 4];
    }
#pragma unroll
    for (int k = 0; k < 4; k++) {
        int ii = tid + k * 256;
        int c = ii >> 4, t4 = ii & 15;
        ((float4*)xs)[ii] = *(const float4*)&x[(b * 64 + c) * T_ + t0 + t4 * 4];
    }
    __syncthreads();

    int tj = tid & 15, ti = tid >> 4;   // 16 j-groups x 16 t-groups
    float acc[4][4];
#pragma unroll
    for (int a = 0; a < 4; a++)
#pragma unroll
        for (int u = 0; u < 4; u++) acc[a][u] = 0.f;

#pragma unroll
    for (int c = 0; c < 64; c++) {
        float4 wv = *(float4*)&ws[c * 64 + tj * 4];
        float4 xv = *(float4*)&xs[c * 64 + ti * 4];
        float wa[4] = {wv.x, wv.y, wv.z, wv.w};
        float xa[4] = {xv.x, xv.y, xv.z, xv.w};
#pragma unroll
        for (int a = 0; a < 4; a++)
#pragma unroll
            for (int u = 0; u < 4; u++) acc[a][u] += wa[a] * xa[u];
    }
#pragma unroll
    for (int a = 0; a < 4; a++) {
        float4 o = make_float4(acc[a][0], acc[a][1], acc[a][2], acc[a][3]);
        *(float4*)&g_qkv[(b * J3 + jg * 64 + tj * 4 + a) * T_ + t0 + ti * 4] = o;
    }
}

// ---------------------------------------------------------------------------
// proj[m, b, r=(h*8+d), kk] = sum_t qkv[b, jrow(r,m), t] * E[t, kk]
// block: 64 rows x 128 kk, split-K over t (8 splits of 512), atomicAdd out.
__global__ void proj_kernel(const float* __restrict__ E) {
    __shared__ __align__(16) float As[64 * 32];    // [r][t]
    __shared__ __align__(16) float Es[32 * 128];   // [t][kk]
    int id = blockIdx.x;
    int kkt = id & 7;  id >>= 3;
    int ts  = id & 7;  id >>= 3;
    int b   = id & 3;  id >>= 2;
    int m   = id;                       // 0=K, 1=V
    int kk0 = kkt * 128;
    int tid = threadIdx.x;
    int tc = tid & 31;                  // 4 cols each
    int tr = tid >> 5;                  // 8 rows: tr*8..tr*8+7

    float acc[8][4];
#pragma unroll
    for (int rr = 0; rr < 8; rr++)
#pragma unroll
        for (int u = 0; u < 4; u++) acc[rr][u] = 0.f;

    for (int ch = 0; ch < 16; ch++) {
        int tbase = ts * 512 + ch * 32;
#pragma unroll
        for (int k = 0; k < 2; k++) {
            int ii = tid + k * 256;             // 512 float4
            int r = ii >> 3, t4 = ii & 7;
            int d = r & 7, h = r >> 3;
            int jrow = d * 24 + 8 * (1 + m) + h;
            ((float4*)As)[ii] = *(const float4*)&g_qkv[(b * J3 + jrow) * T_ + tbase + t4 * 4];
        }
#pragma unroll
        for (int k = 0; k < 4; k++) {
            int ii = tid + k * 256;             // 1024 float4
            int ti = ii >> 5, k4 = ii & 31;
            ((float4*)Es)[ii] = *(const float4*)&E[(tbase + ti) * KP + kk0 + k4 * 4];
        }
        __syncthreads();
#pragma unroll
        for (int t = 0; t < 32; t++) {
            float4 e4 = *(float4*)&Es[t * 128 + tc * 4];
            float ea[4] = {e4.x, e4.y, e4.z, e4.w};
#pragma unroll
            for (int rr = 0; rr < 8; rr++) {
                float a = As[(tr * 8 + rr) * 32 + t];
#pragma unroll
                for (int u = 0; u < 4; u++) acc[rr][u] += a * ea[u];
            }
        }
        __syncthreads();
    }
    int base = (m * B_ + b) * C_ * KP;
#pragma unroll
    for (int rr = 0; rr < 8; rr++) {
        int r = tr * 8 + rr;
#pragma unroll
        for (int u = 0; u < 4; u++)
            atomicAdd(&g_proj[base + r * KP + kk0 + tc * 4 + u], acc[rr][u]);
    }
}

// ---------------------------------------------------------------------------
// Attention: per (b, h, 64-row t-tile). K/V staged in smem as [d][1024].
// warp handles 2 rows per pass; each lane owns j = lane + 32*i (conflict-free).
__global__ void attn_kernel() {
    extern __shared__ __align__(16) float sm[];
    float* ksm = sm;            // [8][1024]
    float* vsm = sm + 8192;     // [8][1024]
    float* qsm = sm + 16384;    // [64][8], pre-scaled

    int id = blockIdx.x;
    int tt0 = id & 63; id >>= 6;
    int h = id & 7;    id >>= 3;
    int b = id;
    int t0 = tt0 * 64;
    int tid = threadIdx.x;

    const float* kg = &g_proj[((0 * B_ + b) * NH + h) * DH * KP];
    const float* vg = &g_proj[((1 * B_ + b) * NH + h) * DH * KP];
#pragma unroll
    for (int k = 0; k < 8; k++) {
        int ii = tid + k * 256;           // 2048 float4 each
        ((float4*)ksm)[ii] = ((const float4*)kg)[ii];
        ((float4*)vsm)[ii] = ((const float4*)vg)[ii];
    }
#pragma unroll
    for (int k = 0; k < 2; k++) {
        int ii = tid + k * 256;           // 512 floats
        int d = ii >> 6, tt = ii & 63;
        qsm[tt * 8 + d] = g_qkv[(b * J3 + d * 24 + h) * T_ + t0 + tt] * 0.35355339059327373f;
    }
    __syncthreads();

    int w = tid >> 5, lane = tid & 31;
#pragma unroll 1
    for (int pass = 0; pass < 4; pass++) {
        int r0 = w * 8 + pass * 2;
        int r1 = r0 + 1;
        float q0[8], q1[8];
#pragma unroll
        for (int d = 0; d < 8; d++) { q0[d] = qsm[r0 * 8 + d]; q1[d] = qsm[r1 * 8 + d]; }

        float p0[32], p1[32];
#pragma unroll
        for (int i = 0; i < 32; i++) {
            int j = lane + (i << 5);
            float s0 = 0.f, s1 = 0.f;
#pragma unroll
            for (int d = 0; d < 8; d++) {
                float kv = ksm[(d << 10) + j];
                s0 += q0[d] * kv; s1 += q1[d] * kv;
            }
            p0[i] = s0; p1[i] = s1;
        }
        float m0 = p0[0], m1 = p1[0];
#pragma unroll
        for (int i = 1; i < 32; i++) { m0 = fmaxf(m0, p0[i]); m1 = fmaxf(m1, p1[i]); }
#pragma unroll
        for (int o = 16; o >= 1; o >>= 1) {
            m0 = fmaxf(m0, __shfl_xor_sync(0xffffffffu, m0, o));
            m1 = fmaxf(m1, __shfl_xor_sync(0xffffffffu, m1, o));
        }
        float l0 = 0.f, l1 = 0.f;
#pragma unroll
        for (int i = 0; i < 32; i++) {
            p0[i] = __expf(p0[i] - m0); l0 += p0[i];
            p1[i] = __expf(p1[i] - m1); l1 += p1[i];
        }
#pragma unroll
        for (int o = 16; o >= 1; o >>= 1) {
            l0 += __shfl_xor_sync(0xffffffffu, l0, o);
            l1 += __shfl_xor_sync(0xffffffffu, l1, o);
        }
        float o0[8], o1[8];
#pragma unroll
        for (int d = 0; d < 8; d++) { o0[d] = 0.f; o1[d] = 0.f; }
#pragma unroll
        for (int i = 0; i < 32; i++) {
            int j = lane + (i << 5);
#pragma unroll
            for (int d = 0; d < 8; d++) {
                float vv = vsm[(d << 10) + j];
                o0[d] += p0[i] * vv; o1[d] += p1[i] * vv;
            }
        }
#pragma unroll
        for (int d = 0; d < 8; d++) {
#pragma unroll
            for (int o = 16; o >= 1; o >>= 1) {
                o0[d] += __shfl_xor_sync(0xffffffffu, o0[d], o);
                o1[d] += __shfl_xor_sync(0xffffffffu, o1[d], o);
            }
        }
        float inv0 = 1.f / l0, inv1 = 1.f / l1;
        float w0v = 0.f, w1v = 0.f;
#pragma unroll
        for (int d = 0; d < 8; d++) {
            if (lane == d)     w0v = o0[d] * inv0;
            if (lane == d + 8) w1v = o1[d] * inv1;
        }
        if (lane < 8)
            g_att[(b * C_ + h * 8 + lane) * T_ + t0 + r0] = w0v;
        else if (lane < 16)
            g_att[(b * C_ + h * 8 + (lane - 8)) * T_ + t0 + r1] = w1v;
    }
}

// ---------------------------------------------------------------------------
// out[b, c, t] = sum_cp g_att[b, cp, t] * W0[cp, c]   (writes NCHW directly)
__global__ void outproj_kernel(const float* __restrict__ W0,
                               float* __restrict__ out) {
    __shared__ __align__(16) float w0s[64 * 64];   // [cp][c]
    __shared__ __align__(16) float as[64 * 64];    // [cp][t]
    int id = blockIdx.x;
    int tt = id & 63;
    int b  = id >> 6;
    int t0 = tt * 64;
    int tid = threadIdx.x;

#pragma unroll
    for (int k = 0; k < 4; k++) {
        int ii = tid + k * 256;
        int cp = ii >> 4, c4 = ii & 15;
        ((float4*)w0s)[ii] = *(const float4*)&W0[cp * 64 + c4 * 4];
    }
#pragma unroll
    for (int k = 0; k < 4; k++) {
        int ii = tid + k * 256;
        int cp = ii >> 4, t4 = ii & 15;
        ((float4*)as)[ii] = *(const float4*)&g_att[(b * 64 + cp) * T_ + t0 + t4 * 4];
    }
    __syncthreads();

    int tc = tid & 15, ti = tid >> 4;
    float acc[4][4];
#pragma unroll
    for (int a = 0; a < 4; a++)
#pragma unroll
        for (int u = 0; u < 4; u++) acc[a][u] = 0.f;
#pragma unroll
    for (int cp = 0; cp < 64; cp++) {
        float4 wv = *(float4*)&w0s[cp * 64 + tc * 4];
        float4 xv = *(float4*)&as[cp * 64 + ti * 4];
        float wa[4] = {wv.x, wv.y, wv.z, wv.w};
        float xa[4] = {xv.x, xv.y, xv.z, xv.w};
#pragma unroll
        for (int a = 0; a < 4; a++)
#pragma unroll
            for (int u = 0; u < 4; u++) acc[a][u] += wa[a] * xa[u];
    }
#pragma unroll
    for (int a = 0; a < 4; a++) {
        float4 o = make_float4(acc[a][0], acc[a][1], acc[a][2], acc[a][3]);
        *(float4*)&out[(b * 64 + tc * 4 + a) * T_ + t0 + ti * 4] = o;
    }
}

// ---------------------------------------------------------------------------
extern "C" void kernel_launch(void* const* d_in, const int* in_sizes, int n_in,
                              void* d_out, int out_size) {
    const float* x    = (const float*)d_in[0];
    const float* Wqkv = (const float*)d_in[5];
    const float* W0   = (const float*)d_in[6];
    const float* E    = (const float*)d_in[7];
    float* out = (float*)d_out;

    const int attn_smem = (16 * 1024 + 512) * 4;   // 67584 B
    cudaFuncSetAttribute(attn_kernel, cudaFuncAttributeMaxDynamicSharedMemorySize, attn_smem);

    zero_proj_kernel<<<512, 256>>>();
    qkv_kernel<<<B_ * 3 * (T_ / 64), 256>>>(x, Wqkv);
    proj_kernel<<<512, 256>>>(E);
    attn_kernel<<<B_ * NH * (T_ / 64), 256, attn_smem>>>();
    outproj_kernel<<<B_ * (T_ / 64), 256>>>(W0, out);
}

// round 3
// speedup vs baseline: 1.4333x; 1.4333x over previous
#include <cuda_runtime.h>
#include <cstdint>
#include <math.h>

#define B_  4
#define C_  64
#define T_  4096
#define NH  8
#define DH  8
#define KP  1024
#define J3  192

// Scratch (device globals; no allocation allowed)
__device__ float g_qkv[B_ * J3 * T_];          // [b][j][t]   j = d*24 + mat*8 + h
__device__ float g_Et[KP * T_];                // [kk][t]  (E transposed)
__device__ float g_kv[2 * B_ * NH * KP * DH];  // [m][b][h][kk][d]  (j-major, d contiguous)
__device__ float g_att[B_ * C_ * T_];          // [b][h*8+d][t]

__device__ __forceinline__ uint32_t f2tf32(float f) {
    uint32_t u;
    asm("cvt.rna.tf32.f32 %0, %1;" : "=r"(u) : "f"(f));
    return u;
}

// ---------------------------------------------------------------------------
// qkv[b, j, t] = sum_c x[b, c, t] * Wqkv[c, j]
// ---------------------------------------------------------------------------
__global__ void qkv_kernel(const float* __restrict__ x,
                           const float* __restrict__ Wqkv) {
    __shared__ __align__(16) float ws[64 * 64];
    __shared__ __align__(16) float xs[64 * 64];
    int id = blockIdx.x;
    int ttile = id & 63; id >>= 6;
    int jg = id % 3;
    int b  = id / 3;
    int t0 = ttile * 64;
    int tid = threadIdx.x;

#pragma unroll
    for (int k = 0; k < 4; k++) {
        int ii = tid + k * 256;
        int c = ii >> 4, j4 = ii & 15;
        ((float4*)ws)[ii] = *(const float4*)&Wqkv[c * J3 + jg * 64 + j4 * 4];
    }
#pragma unroll
    for (int k = 0; k < 4; k++) {
        int ii = tid + k * 256;
        int c = ii >> 4, t4 = ii & 15;
        ((float4*)xs)[ii] = *(const float4*)&x[(b * 64 + c) * T_ + t0 + t4 * 4];
    }
    __syncthreads();

    int tj = tid & 15, ti = tid >> 4;
    float acc[4][4];
#pragma unroll
    for (int a = 0; a < 4; a++)
#pragma unroll
        for (int u = 0; u < 4; u++) acc[a][u] = 0.f;
#pragma unroll
    for (int c = 0; c < 64; c++) {
        float4 wv = *(float4*)&ws[c * 64 + tj * 4];
        float4 xv = *(float4*)&xs[c * 64 + ti * 4];
        float wa[4] = {wv.x, wv.y, wv.z, wv.w};
        float xa[4] = {xv.x, xv.y, xv.z, xv.w};
#pragma unroll
        for (int a = 0; a < 4; a++)
#pragma unroll
            for (int u = 0; u < 4; u++) acc[a][u] += wa[a] * xa[u];
    }
#pragma unroll
    for (int a = 0; a < 4; a++) {
        float4 o = make_float4(acc[a][0], acc[a][1], acc[a][2], acc[a][3]);
        *(float4*)&g_qkv[(b * J3 + jg * 64 + tj * 4 + a) * T_ + t0 + ti * 4] = o;
    }
}

// ---------------------------------------------------------------------------
// Et[kk][t] = E[t][kk]
// ---------------------------------------------------------------------------
__global__ void transpose_E(const float* __restrict__ E) {
    __shared__ float ts[32][33];
    int kk0 = blockIdx.x * 32;
    int t0  = blockIdx.y * 32;
    int c = threadIdx.x & 31, r8 = threadIdx.x >> 5;
#pragma unroll
    for (int k = 0; k < 4; k++) {
        int r = r8 + k * 8;
        ts[r][c] = E[(size_t)(t0 + r) * KP + kk0 + c];
    }
    __syncthreads();
#pragma unroll
    for (int k = 0; k < 4; k++) {
        int r = r8 + k * 8;
        g_Et[(size_t)(kk0 + r) * T_ + t0 + c] = ts[c][r];
    }
}

// ---------------------------------------------------------------------------
// K/V projection GEMM with mma.sync (tf32):
//   D[row][kk] = sum_t A[row][t] * Et[kk][t]    (row.col → D = A * Et^T)
//   rows (512): grow = m*256 + b*64 + (h*8+d); A row = g_qkv[b][d*24+8+m*8+h]
//   block: M=64 (mt 0..7), N=64 (nt 0..15), K chunked by 32.
//   epilogue writes g_kv[m][b][h][kk][d]
// ---------------------------------------------------------------------------
__global__ void __launch_bounds__(256) proj_mma_kernel() {
    __shared__ uint32_t As[64 * 36];
    __shared__ uint32_t Bs[64 * 36];
    int tid = threadIdx.x;
    int w = tid >> 5, lane = tid & 31;
    int mt = blockIdx.x & 7, nt = blockIdx.x >> 3;

    // load addressing: 512 float4 per tile, 2 per thread
    size_t arow[2], brow[2];
    int sts[2];
#pragma unroll
    for (int k = 0; k < 2; k++) {
        int idx = tid + k * 256;
        int row = idx >> 3, c4 = idx & 7;
        int grow = mt * 64 + row;
        int m = grow >> 8, b = (grow >> 6) & 3, r = grow & 63, d = r & 7, hh = r >> 3;
        arow[k] = (size_t)(b * J3 + d * 24 + 8 + m * 8 + hh) * T_ + c4 * 4;
        brow[k] = (size_t)(nt * 64 + row) * T_ + c4 * 4;
        sts[k] = row * 36 + c4 * 4;
    }

    int wm = w & 3, wn = w >> 2;
    int g = lane >> 2, tig = lane & 3;
    float acc[4][4];
#pragma unroll
    for (int ns = 0; ns < 4; ns++)
#pragma unroll
        for (int u = 0; u < 4; u++) acc[ns][u] = 0.f;

    int a_ld0 = (wm * 16 + g) * 36 + tig;
    int a_ld1 = (wm * 16 + g + 8) * 36 + tig;
    int b_ld  = (wn * 32 + g) * 36 + tig;

#pragma unroll 1
    for (int ch = 0; ch < 128; ch++) {
        int co = ch * 32;
#pragma unroll
        for (int k = 0; k < 2; k++) {
            float4 av = *(const float4*)&g_qkv[arow[k] + co];
            float4 bv = *(const float4*)&g_Et[brow[k] + co];
            uint32_t* ap = &As[sts[k]];
            ap[0] = f2tf32(av.x); ap[1] = f2tf32(av.y);
            ap[2] = f2tf32(av.z); ap[3] = f2tf32(av.w);
            uint32_t* bp = &Bs[sts[k]];
            bp[0] = f2tf32(bv.x); bp[1] = f2tf32(bv.y);
            bp[2] = f2tf32(bv.z); bp[3] = f2tf32(bv.w);
        }
        __syncthreads();
#pragma unroll
        for (int ks = 0; ks < 4; ks++) {
            int k0 = ks * 8;
            uint32_t a0 = As[a_ld0 + k0];
            uint32_t a1 = As[a_ld1 + k0];
            uint32_t a2 = As[a_ld0 + k0 + 4];
            uint32_t a3 = As[a_ld1 + k0 + 4];
#pragma unroll
            for (int ns = 0; ns < 4; ns++) {
                uint32_t b0 = Bs[b_ld + ns * 8 * 36 + k0];
                uint32_t b1 = Bs[b_ld + ns * 8 * 36 + k0 + 4];
                asm volatile(
                    "mma.sync.aligned.m16n8k8.row.col.f32.tf32.tf32.f32 "
                    "{%0,%1,%2,%3}, {%4,%5,%6,%7}, {%8,%9}, {%0,%1,%2,%3};"
                    : "+f"(acc[ns][0]), "+f"(acc[ns][1]), "+f"(acc[ns][2]), "+f"(acc[ns][3])
                    : "r"(a0), "r"(a1), "r"(a2), "r"(a3), "r"(b0), "r"(b1));
            }
        }
        __syncthreads();
    }

    // epilogue: row1 = mt*64 + wm*16 + g, row2 = row1 + 8
    int row1 = mt * 64 + wm * 16 + g;
    int row2 = row1 + 8;
    int m1 = row1 >> 8, b1 = (row1 >> 6) & 3, r1 = row1 & 63;
    int m2 = row2 >> 8, b2 = (row2 >> 6) & 3, r2 = row2 & 63;
    size_t base1 = (size_t)((m1 * 4 + b1) * 8 + (r1 >> 3)) * (KP * DH) + (r1 & 7);
    size_t base2 = (size_t)((m2 * 4 + b2) * 8 + (r2 >> 3)) * (KP * DH) + (r2 & 7);
#pragma unroll
    for (int ns = 0; ns < 4; ns++) {
        int n0 = nt * 64 + wn * 32 + ns * 8 + tig * 2;
        g_kv[base1 + (size_t)n0 * 8]       = acc[ns][0];
        g_kv[base1 + (size_t)(n0 + 1) * 8] = acc[ns][1];
        g_kv[base2 + (size_t)n0 * 8]       = acc[ns][2];
        g_kv[base2 + (size_t)(n0 + 1) * 8] = acc[ns][3];
    }
}

// ---------------------------------------------------------------------------
// Attention: block = (b, h, 32-row t-tile), 128 threads (4 warps x 8 rows).
// K/V staged in smem j-major [1024][8]. Streaming softmax without max
// (scores bounded ~|12| in log2 units, exp2 safe). Lane owns j = 32*i + lane.
// ---------------------------------------------------------------------------
__global__ void __launch_bounds__(128, 3) attn_kernel() {
    extern __shared__ __align__(16) float sm[];
    float* ksm = sm;            // [1024][8]
    float* vsm = sm + 8192;     // [1024][8]
    float* qsm = sm + 16384;    // [32][8], pre-scaled by 1/sqrt(8)*log2(e)

    int id = blockIdx.x;
    int tt = id & 127; id >>= 7;
    int h  = id & 7;   id >>= 3;
    int b  = id;
    int t0 = tt * 32;
    int tid = threadIdx.x;

    const float4* kg = (const float4*)&g_kv[(size_t)((0 * 4 + b) * 8 + h) * (KP * DH)];
    const float4* vg = (const float4*)&g_kv[(size_t)((1 * 4 + b) * 8 + h) * (KP * DH)];
#pragma unroll
    for (int k = 0; k < 16; k++) {
        ((float4*)ksm)[tid + k * 128] = kg[tid + k * 128];
        ((float4*)vsm)[tid + k * 128] = vg[tid + k * 128];
    }
#pragma unroll
    for (int k = 0; k < 2; k++) {
        int i = tid + k * 128;
        int d = i >> 5, t = i & 31;
        qsm[t * 8 + d] = g_qkv[(size_t)(b * J3 + d * 24 + h) * T_ + t0 + t] * 0.51006973f;
    }
    __syncthreads();

    int w = tid >> 5, lane = tid & 31;
    float q[8][8], o[8][8], l[8];
#pragma unroll
    for (int rr = 0; rr < 8; rr++) {
#pragma unroll
        for (int d = 0; d < 8; d++) {
            q[rr][d] = qsm[(w * 8 + rr) * 8 + d];
            o[rr][d] = 0.f;
        }
        l[rr] = 0.f;
    }

#pragma unroll 1
    for (int i = 0; i < 32; i++) {
        int j = (i << 5) + lane;
        float4 ka = *(float4*)(ksm + (j << 3));
        float4 kb = *(float4*)(ksm + (j << 3) + 4);
        float4 va = *(float4*)(vsm + (j << 3));
        float4 vb = *(float4*)(vsm + (j << 3) + 4);
#pragma unroll
        for (int rr = 0; rr < 8; rr++) {
            float s = q[rr][0] * ka.x + q[rr][1] * ka.y + q[rr][2] * ka.z + q[rr][3] * ka.w
                    + q[rr][4] * kb.x + q[rr][5] * kb.y + q[rr][6] * kb.z + q[rr][7] * kb.w;
            float pp;
            asm("ex2.approx.f32 %0, %1;" : "=f"(pp) : "f"(s));
            l[rr] += pp;
            o[rr][0] += pp * va.x; o[rr][1] += pp * va.y;
            o[rr][2] += pp * va.z; o[rr][3] += pp * va.w;
            o[rr][4] += pp * vb.x; o[rr][5] += pp * vb.y;
            o[rr][6] += pp * vb.z; o[rr][7] += pp * vb.w;
        }
    }

#pragma unroll
    for (int rr = 0; rr < 8; rr++)
#pragma unroll
        for (int off = 16; off >= 1; off >>= 1)
            l[rr] += __shfl_xor_sync(0xffffffffu, l[rr], off);

    __syncthreads();   // K/V smem now dead; reuse for reduction
    float* red = sm + w * 2176;
#pragma unroll
    for (int rr = 0; rr < 8; rr++)
#pragma unroll
        for (int d = 0; d < 8; d++)
            red[(rr * 8 + d) * 33 + lane] = o[rr][d];
    __syncwarp();

    float s1 = 0.f, s2 = 0.f;
#pragma unroll
    for (int t = 0; t < 32; t++) {
        s1 += red[lane * 33 + t];
        s2 += red[(lane + 32) * 33 + t];
    }
    int rr1 = lane >> 3, d = lane & 7;
    int rr2 = rr1 + 4;
    float o1 = __fdividef(s1, l[rr1]);
    float o2 = __fdividef(s2, l[rr2]);
    size_t ob = (size_t)(b * 64 + h * 8 + d) * T_ + t0 + w * 8;
    g_att[ob + rr1] = o1;
    g_att[ob + rr2] = o2;
}

// ---------------------------------------------------------------------------
// out[b, c, t] = sum_cp g_att[b, cp, t] * W0[cp, c]
// ---------------------------------------------------------------------------
__global__ void outproj_kernel(const float* __restrict__ W0,
                               float* __restrict__ out) {
    __shared__ __align__(16) float w0s[64 * 64];
    __shared__ __align__(16) float as[64 * 64];
    int id = blockIdx.x;
    int tt = id & 63;
    int b  = id >> 6;
    int t0 = tt * 64;
    int tid = threadIdx.x;

#pragma unroll
    for (int k = 0; k < 4; k++) {
        int ii = tid + k * 256;
        int cp = ii >> 4, c4 = ii & 15;
        ((float4*)w0s)[ii] = *(const float4*)&W0[cp * 64 + c4 * 4];
    }
#pragma unroll
    for (int k = 0; k < 4; k++) {
        int ii = tid + k * 256;
        int cp = ii >> 4, t4 = ii & 15;
        ((float4*)as)[ii] = *(const float4*)&g_att[(b * 64 + cp) * T_ + t0 + t4 * 4];
    }
    __syncthreads();

    int tc = tid & 15, ti = tid >> 4;
    float acc[4][4];
#pragma unroll
    for (int a = 0; a < 4; a++)
#pragma unroll
        for (int u = 0; u < 4; u++) acc[a][u] = 0.f;
#pragma unroll
    for (int cp = 0; cp < 64; cp++) {
        float4 wv = *(float4*)&w0s[cp * 64 + tc * 4];
        float4 xv = *(float4*)&as[cp * 64 + ti * 4];
        float wa[4] = {wv.x, wv.y, wv.z, wv.w};
        float xa[4] = {xv.x, xv.y, xv.z, xv.w};
#pragma unroll
        for (int a = 0; a < 4; a++)
#pragma unroll
            for (int u = 0; u < 4; u++) acc[a][u] += wa[a] * xa[u];
    }
#pragma unroll
    for (int a = 0; a < 4; a++) {
        float4 o = make_float4(acc[a][0], acc[a][1], acc[a][2], acc[a][3]);
        *(float4*)&out[(b * 64 + tc * 4 + a) * T_ + t0 + ti * 4] = o;
    }
}

// ---------------------------------------------------------------------------
extern "C" void kernel_launch(void* const* d_in, const int* in_sizes, int n_in,
                              void* d_out, int out_size) {
    const float* x    = (const float*)d_in[0];
    const float* Wqkv = (const float*)d_in[5];
    const float* W0   = (const float*)d_in[6];
    const float* E    = (const float*)d_in[7];
    float* out = (float*)d_out;

    const int attn_smem = (2 * 8192 + 256) * 4;            // 66560 B
    cudaFuncSetAttribute(attn_kernel, cudaFuncAttributeMaxDynamicSharedMemorySize, attn_smem);

    qkv_kernel<<<B_ * 3 * (T_ / 64), 256>>>(x, Wqkv);
    transpose_E<<<dim3(KP / 32, T_ / 32), 256>>>(E);
    proj_mma_kernel<<<128, 256>>>();
    attn_kernel<<<B_ * NH * (T_ / 32), 128, attn_smem>>>();
    outproj_kernel<<<B_ * (T_ / 64), 256>>>(W0, out);
}

// round 4
// speedup vs baseline: 2.4079x; 1.6800x over previous
#include <cuda_runtime.h>
#include <cuda_fp16.h>
#include <cstdint>
#include <math.h>

#define B_  4
#define C_  64
#define T_  4096
#define NH  8
#define DH  8
#define KP  1024
#define J3  192

// Scratch (device globals; no allocation allowed)
__device__ float  g_qkv[B_ * J3 * T_];          // q rows (mat==0) valid: [b][d*24+h][t]
__device__ __half g_A16[512 * T_];              // K/V rows fp16: grow = m*256 + b*64 + h*8 + d
__device__ __half g_Eth[KP * T_];               // Et fp16 [kk][t]
__device__ float  g_kv[2 * B_ * NH * KP * DH];  // [m][b][h][kk][d]
__device__ float  g_att[B_ * C_ * T_];          // [b][h*8+d][t]

__device__ __forceinline__ uint32_t smem_to_u32(const void* p) {
    uint32_t a;
    asm("{ .reg .u64 t; cvta.to.shared.u64 t, %1; cvt.u32.u64 %0, t; }" : "=r"(a) : "l"(p));
    return a;
}
__device__ __forceinline__ void cp16(uint32_t dst, const void* src) {
    asm volatile("cp.async.cg.shared.global [%0], [%1], 16;" :: "r"(dst), "l"(src));
}
#define CP_COMMIT() asm volatile("cp.async.commit_group;" ::: "memory")
#define CP_WAIT2()  asm volatile("cp.async.wait_group 2;" ::: "memory")

// ---------------------------------------------------------------------------
// zero g_kv (2MB) for split-K atomic accumulation
// ---------------------------------------------------------------------------
__global__ void zero_kv_kernel() {
    int i = blockIdx.x * blockDim.x + threadIdx.x;   // 131072 float4
    ((float4*)g_kv)[i] = make_float4(0.f, 0.f, 0.f, 0.f);
}

// ---------------------------------------------------------------------------
// qkv[b, j, t] = sum_c x[b, c, t] * Wqkv[c, j]
// mat==0 rows -> g_qkv fp32 ; mat>0 rows -> g_A16 fp16
// ---------------------------------------------------------------------------
__global__ void qkv_kernel(const float* __restrict__ x,
                           const float* __restrict__ Wqkv) {
    __shared__ __align__(16) float ws[64 * 64];
    __shared__ __align__(16) float xs[64 * 64];
    int id = blockIdx.x;
    int ttile = id & 63; id >>= 6;
    int jg = id % 3;
    int b  = id / 3;
    int t0 = ttile * 64;
    int tid = threadIdx.x;

#pragma unroll
    for (int k = 0; k < 4; k++) {
        int ii = tid + k * 256;
        int c = ii >> 4, j4 = ii & 15;
        ((float4*)ws)[ii] = *(const float4*)&Wqkv[c * J3 + jg * 64 + j4 * 4];
    }
#pragma unroll
    for (int k = 0; k < 4; k++) {
        int ii = tid + k * 256;
        int c = ii >> 4, t4 = ii & 15;
        ((float4*)xs)[ii] = *(const float4*)&x[(b * 64 + c) * T_ + t0 + t4 * 4];
    }
    __syncthreads();

    int tj = tid & 15, ti = tid >> 4;
    float acc[4][4];
#pragma unroll
    for (int a = 0; a < 4; a++)
#pragma unroll
        for (int u = 0; u < 4; u++) acc[a][u] = 0.f;
#pragma unroll
    for (int c = 0; c < 64; c++) {
        float4 wv = *(float4*)&ws[c * 64 + tj * 4];
        float4 xv = *(float4*)&xs[c * 64 + ti * 4];
        float wa[4] = {wv.x, wv.y, wv.z, wv.w};
        float xa[4] = {xv.x, xv.y, xv.z, xv.w};
#pragma unroll
        for (int a = 0; a < 4; a++)
#pragma unroll
            for (int u = 0; u < 4; u++) acc[a][u] += wa[a] * xa[u];
    }
#pragma unroll
    for (int a = 0; a < 4; a++) {
        int j = jg * 64 + tj * 4 + a;
        int d = j / 24, rem = j % 24;
        int mat = rem >> 3, h = rem & 7;
        int t = t0 + ti * 4;
        if (mat == 0) {
            float4 o = make_float4(acc[a][0], acc[a][1], acc[a][2], acc[a][3]);
            *(float4*)&g_qkv[(size_t)(b * J3 + j) * T_ + t] = o;
        } else {
            int grow = (mat - 1) * 256 + b * 64 + h * 8 + d;
            __half2 p0 = __floats2half2_rn(acc[a][0], acc[a][1]);
            __half2 p1 = __floats2half2_rn(acc[a][2], acc[a][3]);
            __half2* dst = (__half2*)&g_A16[(size_t)grow * T_ + t];
            dst[0] = p0; dst[1] = p1;
        }
    }
}

// ---------------------------------------------------------------------------
// Eth[kk][t] = (half)E[t][kk]
// ---------------------------------------------------------------------------
__global__ void transpose_E(const float* __restrict__ E) {
    __shared__ float ts[32][33];
    int kk0 = blockIdx.x * 32;
    int t0  = blockIdx.y * 32;
    int c = threadIdx.x & 31, r8 = threadIdx.x >> 5;
#pragma unroll
    for (int k = 0; k < 4; k++) {
        int r = r8 + k * 8;
        ts[r][c] = E[(size_t)(t0 + r) * KP + kk0 + c];
    }
    __syncthreads();
#pragma unroll
    for (int k = 0; k < 4; k++) {
        int r = r8 + k * 8;
        g_Eth[(size_t)(kk0 + r) * T_ + t0 + c] = __float2half_rn(ts[c][r]);
    }
}

// ---------------------------------------------------------------------------
// K/V projection GEMM, fp16 HMMA m16n8k16 + cp.async 3-stage pipeline.
//   D[row][kk] = sum_t A16[row][t] * Eth[kk][t]
//   block tile M=128 x N=64, split-K=2 (2048 each), 128 threads (4 warps m64n32)
//   epilogue: atomicAdd into g_kv[m][b][h][kk][d]
// smem stage: A 128 rows x 144B (pitch 36 words) = 18432, B 64 x 144 = 9216.
// ---------------------------------------------------------------------------
#define PJ_STAGE 27648
#define PJ_BOFF  18432
#define PJ_CH    32

__global__ void __launch_bounds__(128) proj_mma_kernel() {
    extern __shared__ __align__(16) char sm[];
    uint32_t sb = smem_to_u32(sm);
    int tid = threadIdx.x, lane = tid & 31, w = tid >> 5;
    int wm = w & 1, wn = w >> 1;
    int bx = blockIdx.x;
    int mt = bx & 3, nt = (bx >> 2) & 15, ksp = bx >> 6;
    int koff0 = ksp * 2048;

    int rb = tid >> 3, cc = tid & 7;           // chunk assignment
    const __half* gA = &g_A16[(size_t)(mt * 128 + rb) * T_ + koff0 + cc * 8];
    const __half* gB = &g_Eth[(size_t)(nt * 64 + rb) * T_ + koff0 + cc * 8];
    uint32_t dA = sb + rb * 144 + cc * 16;
    uint32_t dB = sb + PJ_BOFF + rb * 144 + cc * 16;

    int g = lane >> 2, tig = lane & 3;
    float acc[4][4][4];
#pragma unroll
    for (int fm = 0; fm < 4; fm++)
#pragma unroll
        for (int fn = 0; fn < 4; fn++)
#pragma unroll
            for (int u = 0; u < 4; u++) acc[fm][fn][u] = 0.f;

    // issue(ch, st): A 8 chunks (rows rb+16k), B 4 chunks
#define PJ_ISSUE(ch, st) do {                                                   \
    uint32_t sa = dA + (st) * PJ_STAGE;                                         \
    uint32_t sbp = dB + (st) * PJ_STAGE;                                        \
    const __half* pa = gA + (ch) * 64;                                          \
    const __half* pb = gB + (ch) * 64;                                          \
    _Pragma("unroll")                                                           \
    for (int k = 0; k < 8; k++)                                                 \
        cp16(sa + k * (16 * 144), pa + (size_t)(16 * k) * T_);                  \
    _Pragma("unroll")                                                           \
    for (int k = 0; k < 4; k++)                                                 \
        cp16(sbp + k * (16 * 144), pb + (size_t)(16 * k) * T_);                 \
} while (0)

    PJ_ISSUE(0, 0); CP_COMMIT();
    PJ_ISSUE(1, 1); CP_COMMIT();

    uint32_t a_base = sb + (wm * 64 + g) * 144 + tig * 4;
    uint32_t b_base = sb + PJ_BOFF + (wn * 32 + g) * 144 + tig * 4;

#pragma unroll 1
    for (int ch = 0; ch < PJ_CH; ch++) {
        if (ch + 2 < PJ_CH) { PJ_ISSUE(ch + 2, (ch + 2) % 3); }
        CP_COMMIT();
        CP_WAIT2();
        __syncthreads();
        uint32_t so = (ch % 3) * PJ_STAGE;
#pragma unroll
        for (int ks = 0; ks < 4; ks++) {
            uint32_t a[4][4];
#pragma unroll
            for (int fm = 0; fm < 4; fm++) {
                uint32_t r0 = a_base + so + fm * (16 * 144) + ks * 32;
                a[fm][0] = *(uint32_t*)(sm + (r0 - sb));
                a[fm][1] = *(uint32_t*)(sm + (r0 - sb) + 8 * 144);
                a[fm][2] = *(uint32_t*)(sm + (r0 - sb) + 16);
                a[fm][3] = *(uint32_t*)(sm + (r0 - sb) + 8 * 144 + 16);
            }
            uint32_t b[4][2];
#pragma unroll
            for (int fn = 0; fn < 4; fn++) {
                uint32_t r0 = b_base + so + fn * (8 * 144) + ks * 32;
                b[fn][0] = *(uint32_t*)(sm + (r0 - sb));
                b[fn][1] = *(uint32_t*)(sm + (r0 - sb) + 16);
            }
#pragma unroll
            for (int fm = 0; fm < 4; fm++)
#pragma unroll
                for (int fn = 0; fn < 4; fn++)
                    asm volatile(
                        "mma.sync.aligned.m16n8k16.row.col.f32.f16.f16.f32 "
                        "{%0,%1,%2,%3}, {%4,%5,%6,%7}, {%8,%9}, {%0,%1,%2,%3};"
                        : "+f"(acc[fm][fn][0]), "+f"(acc[fm][fn][1]),
                          "+f"(acc[fm][fn][2]), "+f"(acc[fm][fn][3])
                        : "r"(a[fm][0]), "r"(a[fm][1]), "r"(a[fm][2]), "r"(a[fm][3]),
                          "r"(b[fn][0]), "r"(b[fn][1]));
        }
        __syncthreads();
    }

    // epilogue: atomicAdd
#pragma unroll
    for (int fm = 0; fm < 4; fm++) {
        int grow0 = mt * 128 + wm * 64 + fm * 16 + g;
#pragma unroll
        for (int half_m = 0; half_m < 2; half_m++) {
            int grow = grow0 + half_m * 8;
            int m = grow >> 8, b = (grow >> 6) & 3, r = grow & 63;
            size_t base = (size_t)((m * 4 + b) * 8 + (r >> 3)) * (KP * DH) + (r & 7);
#pragma unroll
            for (int fn = 0; fn < 4; fn++) {
                int kk = nt * 64 + wn * 32 + fn * 8 + 2 * tig;
                atomicAdd(&g_kv[base + (size_t)kk * 8],       acc[fm][fn][half_m * 2]);
                atomicAdd(&g_kv[base + (size_t)(kk + 1) * 8], acc[fm][fn][half_m * 2 + 1]);
            }
        }
    }
}

// ---------------------------------------------------------------------------
// Attention: block = (b, h, 32-row t-tile), 128 threads (4 warps x 8 rows).
// K/V staged in smem j-major [1024][8]. Streaming softmax without max.
// ---------------------------------------------------------------------------
__global__ void __launch_bounds__(128, 3) attn_kernel() {
    extern __shared__ __align__(16) float smf[];
    float* ksm = smf;            // [1024][8]
    float* vsm = smf + 8192;     // [1024][8]
    float* qsm = smf + 16384;    // [32][8]

    int id = blockIdx.x;
    int tt = id & 127; id >>= 7;
    int h  = id & 7;   id >>= 3;
    int b  = id;
    int t0 = tt * 32;
    int tid = threadIdx.x;

    const float4* kg = (const float4*)&g_kv[(size_t)((0 * 4 + b) * 8 + h) * (KP * DH)];
    const float4* vg = (const float4*)&g_kv[(size_t)((1 * 4 + b) * 8 + h) * (KP * DH)];
#pragma unroll
    for (int k = 0; k < 16; k++) {
        ((float4*)ksm)[tid + k * 128] = kg[tid + k * 128];
        ((float4*)vsm)[tid + k * 128] = vg[tid + k * 128];
    }
#pragma unroll
    for (int k = 0; k < 2; k++) {
        int i = tid + k * 128;
        int d = i >> 5, t = i & 31;
        qsm[t * 8 + d] = g_qkv[(size_t)(b * J3 + d * 24 + h) * T_ + t0 + t] * 0.51006973f;
    }
    __syncthreads();

    int w = tid >> 5, lane = tid & 31;
    float q[8][8], o[8][8], l[8];
#pragma unroll
    for (int rr = 0; rr < 8; rr++) {
#pragma unroll
        for (int d = 0; d < 8; d++) {
            q[rr][d] = qsm[(w * 8 + rr) * 8 + d];
            o[rr][d] = 0.f;
        }
        l[rr] = 0.f;
    }

#pragma unroll 1
    for (int i = 0; i < 32; i++) {
        int j = (i << 5) + lane;
        float4 ka = *(float4*)(ksm + (j << 3));
        float4 kb = *(float4*)(ksm + (j << 3) + 4);
        float4 va = *(float4*)(vsm + (j << 3));
        float4 vb = *(float4*)(vsm + (j << 3) + 4);
#pragma unroll
        for (int rr = 0; rr < 8; rr++) {
            float s = q[rr][0] * ka.x + q[rr][1] * ka.y + q[rr][2] * ka.z + q[rr][3] * ka.w
                    + q[rr][4] * kb.x + q[rr][5] * kb.y + q[rr][6] * kb.z + q[rr][7] * kb.w;
            float pp;
            asm("ex2.approx.f32 %0, %1;" : "=f"(pp) : "f"(s));
            l[rr] += pp;
            o[rr][0] += pp * va.x; o[rr][1] += pp * va.y;
            o[rr][2] += pp * va.z; o[rr][3] += pp * va.w;
            o[rr][4] += pp * vb.x; o[rr][5] += pp * vb.y;
            o[rr][6] += pp * vb.z; o[rr][7] += pp * vb.w;
        }
    }

#pragma unroll
    for (int rr = 0; rr < 8; rr++)
#pragma unroll
        for (int off = 16; off >= 1; off >>= 1)
            l[rr] += __shfl_xor_sync(0xffffffffu, l[rr], off);

    __syncthreads();
    float* red = smf + w * 2176;
#pragma unroll
    for (int rr = 0; rr < 8; rr++)
#pragma unroll
        for (int d = 0; d < 8; d++)
            red[(rr * 8 + d) * 33 + lane] = o[rr][d];
    __syncwarp();

    float s1 = 0.f, s2 = 0.f;
#pragma unroll
    for (int t = 0; t < 32; t++) {
        s1 += red[lane * 33 + t];
        s2 += red[(lane + 32) * 33 + t];
    }
    int rr1 = lane >> 3, d = lane & 7;
    int rr2 = rr1 + 4;
    float o1 = __fdividef(s1, l[rr1]);
    float o2 = __fdividef(s2, l[rr2]);
    size_t ob = (size_t)(b * 64 + h * 8 + d) * T_ + t0 + w * 8;
    g_att[ob + rr1] = o1;
    g_att[ob + rr2] = o2;
}

// ---------------------------------------------------------------------------
// out[b, c, t] = sum_cp g_att[b, cp, t] * W0[cp, c]
// ---------------------------------------------------------------------------
__global__ void outproj_kernel(const float* __restrict__ W0,
                               float* __restrict__ out) {
    __shared__ __align__(16) float w0s[64 * 64];
    __shared__ __align__(16) float as[64 * 64];
    int id = blockIdx.x;
    int tt = id & 63;
    int b  = id >> 6;
    int t0 = tt * 64;
    int tid = threadIdx.x;

#pragma unroll
    for (int k = 0; k < 4; k++) {
        int ii = tid + k * 256;
        int cp = ii >> 4, c4 = ii & 15;
        ((float4*)w0s)[ii] = *(const float4*)&W0[cp * 64 + c4 * 4];
    }
#pragma unroll
    for (int k = 0; k < 4; k++) {
        int ii = tid + k * 256;
        int cp = ii >> 4, t4 = ii & 15;
        ((float4*)as)[ii] = *(const float4*)&g_att[(b * 64 + cp) * T_ + t0 + t4 * 4];
    }
    __syncthreads();

    int tc = tid & 15, ti = tid >> 4;
    float acc[4][4];
#pragma unroll
    for (int a = 0; a < 4; a++)
#pragma unroll
        for (int u = 0; u < 4; u++) acc[a][u] = 0.f;
#pragma unroll
    for (int cp = 0; cp < 64; cp++) {
        float4 wv = *(float4*)&w0s[cp * 64 + tc * 4];
        float4 xv = *(float4*)&as[cp * 64 + ti * 4];
        float wa[4] = {wv.x, wv.y, wv.z, wv.w};
        float xa[4] = {xv.x, xv.y, xv.z, xv.w};
#pragma unroll
        for (int a = 0; a < 4; a++)
#pragma unroll
            for (int u = 0; u < 4; u++) acc[a][u] += wa[a] * xa[u];
    }
#pragma unroll
    for (int a = 0; a < 4; a++) {
        float4 o = make_float4(acc[a][0], acc[a][1], acc[a][2], acc[a][3]);
        *(float4*)&out[(b * 64 + tc * 4 + a) * T_ + t0 + ti * 4] = o;
    }
}

// ---------------------------------------------------------------------------
extern "C" void kernel_launch(void* const* d_in, const int* in_sizes, int n_in,
                              void* d_out, int out_size) {
    const float* x    = (const float*)d_in[0];
    const float* Wqkv = (const float*)d_in[5];
    const float* W0   = (const float*)d_in[6];
    const float* E    = (const float*)d_in[7];
    float* out = (float*)d_out;

    const int proj_smem = 3 * PJ_STAGE;                    // 82944 B
    const int attn_smem = (2 * 8192 + 256) * 4;            // 66560 B
    cudaFuncSetAttribute(proj_mma_kernel, cudaFuncAttributeMaxDynamicSharedMemorySize, proj_smem);
    cudaFuncSetAttribute(attn_kernel, cudaFuncAttributeMaxDynamicSharedMemorySize, attn_smem);

    zero_kv_kernel<<<512, 256>>>();
    qkv_kernel<<<B_ * 3 * (T_ / 64), 256>>>(x, Wqkv);
    transpose_E<<<dim3(KP / 32, T_ / 32), 256>>>(E);
    proj_mma_kernel<<<128, 128, proj_smem>>>();
    attn_kernel<<<B_ * NH * (T_ / 32), 128, attn_smem>>>();
    outproj_kernel<<<B_ * (T_ / 64), 256>>>(W0, out);
}

// round 7
// speedup vs baseline: 4.1502x; 1.7236x over previous
#include <cuda_runtime.h>
#include <cuda_fp16.h>
#include <cstdint>
#include <math.h>

#define B_  4
#define C_  64
#define T_  4096
#define NH  8
#define DH  8
#define KP  1024
#define J3  192

// Scratch (device globals; no allocation allowed)
__device__ float  g_qkv[B_ * J3 * T_];          // q rows (mat==0) valid: [b][d*24+h][t]
__device__ __half g_A16[512 * T_];              // K/V rows fp16: grow = m*256 + b*64 + h*8 + d
__device__ __half g_Eth[KP * T_];               // Et fp16 [kk][t]
__device__ float  g_kv[2 * B_ * NH * KP * DH];  // [m][b][h][kk][d]
__device__ __half g_k16[B_ * NH * KP * DH];     // [b][h][kk][d]  fp16
__device__ __half g_v16[B_ * NH * DH * KP];     // [b][h][d][kk]  fp16
__device__ float  g_att[B_ * C_ * T_];          // [b][h*8+d][t]

__device__ __forceinline__ uint32_t smem_to_u32(const void* p) {
    uint32_t a;
    asm("{ .reg .u64 t; cvta.to.shared.u64 t, %1; cvt.u32.u64 %0, t; }" : "=r"(a) : "l"(p));
    return a;
}
__device__ __forceinline__ void cp16(uint32_t dst, const void* src) {
    asm volatile("cp.async.cg.shared.global [%0], [%1], 16;" :: "r"(dst), "l"(src));
}
#define CP_COMMIT() asm volatile("cp.async.commit_group;" ::: "memory")
#define CP_WAIT2()  asm volatile("cp.async.wait_group 2;" ::: "memory")

// ---------------------------------------------------------------------------
__global__ void zero_kv_kernel() {
    int i = blockIdx.x * blockDim.x + threadIdx.x;   // 131072 float4
    ((float4*)g_kv)[i] = make_float4(0.f, 0.f, 0.f, 0.f);
}

// ---------------------------------------------------------------------------
// qkv[b, j, t] = sum_c x[b, c, t] * Wqkv[c, j]
// mat==0 rows -> g_qkv fp32 ; mat>0 rows -> g_A16 fp16
// ---------------------------------------------------------------------------
__global__ void qkv_kernel(const float* __restrict__ x,
                           const float* __restrict__ Wqkv) {
    __shared__ __align__(16) float ws[64 * 64];
    __shared__ __align__(16) float xs[64 * 64];
    int id = blockIdx.x;
    int ttile = id & 63; id >>= 6;
    int jg = id % 3;
    int b  = id / 3;
    int t0 = ttile * 64;
    int tid = threadIdx.x;

#pragma unroll
    for (int k = 0; k < 4; k++) {
        int ii = tid + k * 256;
        int c = ii >> 4, j4 = ii & 15;
        ((float4*)ws)[ii] = *(const float4*)&Wqkv[c * J3 + jg * 64 + j4 * 4];
    }
#pragma unroll
    for (int k = 0; k < 4; k++) {
        int ii = tid + k * 256;
        int c = ii >> 4, t4 = ii & 15;
        ((float4*)xs)[ii] = *(const float4*)&x[(b * 64 + c) * T_ + t0 + t4 * 4];
    }
    __syncthreads();

    int tj = tid & 15, ti = tid >> 4;
    float acc[4][4];
#pragma unroll
    for (int a = 0; a < 4; a++)
#pragma unroll
        for (int u = 0; u < 4; u++) acc[a][u] = 0.f;
#pragma unroll
    for (int c = 0; c < 64; c++) {
        float4 wv = *(float4*)&ws[c * 64 + tj * 4];
        float4 xv = *(float4*)&xs[c * 64 + ti * 4];
        float wa[4] = {wv.x, wv.y, wv.z, wv.w};
        float xa[4] = {xv.x, xv.y, xv.z, xv.w};
#pragma unroll
        for (int a = 0; a < 4; a++)
#pragma unroll
            for (int u = 0; u < 4; u++) acc[a][u] += wa[a] * xa[u];
    }
#pragma unroll
    for (int a = 0; a < 4; a++) {
        int j = jg * 64 + tj * 4 + a;
        int d = j / 24, rem = j % 24;
        int mat = rem >> 3, h = rem & 7;
        int t = t0 + ti * 4;
        if (mat == 0) {
            float4 o = make_float4(acc[a][0], acc[a][1], acc[a][2], acc[a][3]);
            *(float4*)&g_qkv[(size_t)(b * J3 + j) * T_ + t] = o;
        } else {
            int grow = (mat - 1) * 256 + b * 64 + h * 8 + d;
            __half2 p0 = __floats2half2_rn(acc[a][0], acc[a][1]);
            __half2 p1 = __floats2half2_rn(acc[a][2], acc[a][3]);
            __half2* dst = (__half2*)&g_A16[(size_t)grow * T_ + t];
            dst[0] = p0; dst[1] = p1;
        }
    }
}

// ---------------------------------------------------------------------------
// Eth[kk][t] = (half)E[t][kk]
// ---------------------------------------------------------------------------
__global__ void transpose_E(const float* __restrict__ E) {
    __shared__ float ts[32][33];
    int kk0 = blockIdx.x * 32;
    int t0  = blockIdx.y * 32;
    int c = threadIdx.x & 31, r8 = threadIdx.x >> 5;
#pragma unroll
    for (int k = 0; k < 4; k++) {
        int r = r8 + k * 8;
        ts[r][c] = E[(size_t)(t0 + r) * KP + kk0 + c];
    }
    __syncthreads();
#pragma unroll
    for (int k = 0; k < 4; k++) {
        int r = r8 + k * 8;
        g_Eth[(size_t)(kk0 + r) * T_ + t0 + c] = __float2half_rn(ts[c][r]);
    }
}

// ---------------------------------------------------------------------------
// K/V projection GEMM, fp16 HMMA m16n8k16 + cp.async 3-stage pipeline.
// ---------------------------------------------------------------------------
#define PJ_STAGE 27648
#define PJ_BOFF  18432
#define PJ_CH    32

__global__ void __launch_bounds__(128) proj_mma_kernel() {
    extern __shared__ __align__(16) char sm[];
    uint32_t sb = smem_to_u32(sm);
    int tid = threadIdx.x, lane = tid & 31, w = tid >> 5;
    int wm = w & 1, wn = w >> 1;
    int bx = blockIdx.x;
    int mt = bx & 3, nt = (bx >> 2) & 15, ksp = bx >> 6;
    int koff0 = ksp * 2048;

    int rb = tid >> 3, cc = tid & 7;
    const __half* gA = &g_A16[(size_t)(mt * 128 + rb) * T_ + koff0 + cc * 8];
    const __half* gB = &g_Eth[(size_t)(nt * 64 + rb) * T_ + koff0 + cc * 8];
    uint32_t dA = sb + rb * 144 + cc * 16;
    uint32_t dB = sb + PJ_BOFF + rb * 144 + cc * 16;

    int g = lane >> 2, tig = lane & 3;
    float acc[4][4][4];
#pragma unroll
    for (int fm = 0; fm < 4; fm++)
#pragma unroll
        for (int fn = 0; fn < 4; fn++)
#pragma unroll
            for (int u = 0; u < 4; u++) acc[fm][fn][u] = 0.f;

#define PJ_ISSUE(ch, st) do {                                                   \
    uint32_t sa = dA + (st) * PJ_STAGE;                                         \
    uint32_t sbp = dB + (st) * PJ_STAGE;                                        \
    const __half* pa = gA + (ch) * 64;                                          \
    const __half* pb = gB + (ch) * 64;                                          \
    _Pragma("unroll")                                                           \
    for (int k = 0; k < 8; k++)                                                 \
        cp16(sa + k * (16 * 144), pa + (size_t)(16 * k) * T_);                  \
    _Pragma("unroll")                                                           \
    for (int k = 0; k < 4; k++)                                                 \
        cp16(sbp + k * (16 * 144), pb + (size_t)(16 * k) * T_);                 \
} while (0)

    PJ_ISSUE(0, 0); CP_COMMIT();
    PJ_ISSUE(1, 1); CP_COMMIT();

    uint32_t a_base = sb + (wm * 64 + g) * 144 + tig * 4;
    uint32_t b_base = sb + PJ_BOFF + (wn * 32 + g) * 144 + tig * 4;

#pragma unroll 1
    for (int ch = 0; ch < PJ_CH; ch++) {
        if (ch + 2 < PJ_CH) { PJ_ISSUE(ch + 2, (ch + 2) % 3); }
        CP_COMMIT();
        CP_WAIT2();
        __syncthreads();
        uint32_t so = (ch % 3) * PJ_STAGE;
#pragma unroll
        for (int ks = 0; ks < 4; ks++) {
            uint32_t a[4][4];
#pragma unroll
            for (int fm = 0; fm < 4; fm++) {
                uint32_t r0 = a_base + so + fm * (16 * 144) + ks * 32;
                a[fm][0] = *(uint32_t*)(sm + (r0 - sb));
                a[fm][1] = *(uint32_t*)(sm + (r0 - sb) + 8 * 144);
                a[fm][2] = *(uint32_t*)(sm + (r0 - sb) + 16);
                a[fm][3] = *(uint32_t*)(sm + (r0 - sb) + 8 * 144 + 16);
            }
            uint32_t b[4][2];
#pragma unroll
            for (int fn = 0; fn < 4; fn++) {
                uint32_t r0 = b_base + so + fn * (8 * 144) + ks * 32;
                b[fn][0] = *(uint32_t*)(sm + (r0 - sb));
                b[fn][1] = *(uint32_t*)(sm + (r0 - sb) + 16);
            }
#pragma unroll
            for (int fm = 0; fm < 4; fm++)
#pragma unroll
                for (int fn = 0; fn < 4; fn++)
                    asm volatile(
                        "mma.sync.aligned.m16n8k16.row.col.f32.f16.f16.f32 "
                        "{%0,%1,%2,%3}, {%4,%5,%6,%7}, {%8,%9}, {%0,%1,%2,%3};"
                        : "+f"(acc[fm][fn][0]), "+f"(acc[fm][fn][1]),
                          "+f"(acc[fm][fn][2]), "+f"(acc[fm][fn][3])
                        : "r"(a[fm][0]), "r"(a[fm][1]), "r"(a[fm][2]), "r"(a[fm][3]),
                          "r"(b[fn][0]), "r"(b[fn][1]));
        }
        __syncthreads();
    }

#pragma unroll
    for (int fm = 0; fm < 4; fm++) {
        int grow0 = mt * 128 + wm * 64 + fm * 16 + g;
#pragma unroll
        for (int half_m = 0; half_m < 2; half_m++) {
            int grow = grow0 + half_m * 8;
            int m = grow >> 8, b = (grow >> 6) & 3, r = grow & 63;
            size_t base = (size_t)((m * 4 + b) * 8 + (r >> 3)) * (KP * DH) + (r & 7);
#pragma unroll
            for (int fn = 0; fn < 4; fn++) {
                int kk = nt * 64 + wn * 32 + fn * 8 + 2 * tig;
                atomicAdd(&g_kv[base + (size_t)kk * 8],       acc[fm][fn][half_m * 2]);
                atomicAdd(&g_kv[base + (size_t)(kk + 1) * 8], acc[fm][fn][half_m * 2 + 1]);
            }
        }
    }
}

// ---------------------------------------------------------------------------
// Convert g_kv (f32) -> g_k16 ([b][h][kk][d], fp16), g_v16 ([b][h][d][kk], fp16)
// ---------------------------------------------------------------------------
__global__ void kv16_kernel() {
    int bh = blockIdx.x;                 // b*8+h
    int b = bh >> 3, h = bh & 7;
    const float* ks = &g_kv[(size_t)((0 * 4 + b) * 8 + h) * (KP * DH)];
    const float* vs = &g_kv[(size_t)((1 * 4 + b) * 8 + h) * (KP * DH)];
    __half* kd = &g_k16[(size_t)bh * (KP * DH)];
    __half* vd = &g_v16[(size_t)bh * (DH * KP)];
#pragma unroll 1
    for (int ch = 0; ch < 4; ch++) {
        int kk = ch * 256 + threadIdx.x;
        float4 k0 = *(const float4*)&ks[kk * 8];
        float4 k1 = *(const float4*)&ks[kk * 8 + 4];
        __half2 kh[4];
        kh[0] = __floats2half2_rn(k0.x, k0.y);
        kh[1] = __floats2half2_rn(k0.z, k0.w);
        kh[2] = __floats2half2_rn(k1.x, k1.y);
        kh[3] = __floats2half2_rn(k1.z, k1.w);
        *(uint4*)&kd[kk * 8] = *(uint4*)kh;
        float4 v0 = *(const float4*)&vs[kk * 8];
        float4 v1 = *(const float4*)&vs[kk * 8 + 4];
        float vv[8] = {v0.x, v0.y, v0.z, v0.w, v1.x, v1.y, v1.z, v1.w};
#pragma unroll
        for (int d = 0; d < 8; d++)
            vd[d * KP + kk] = __float2half_rn(vv[d]);
    }
}

// ---------------------------------------------------------------------------
// Attention on HMMA: block = (b, h, 128-row t-tile), 256 threads (8 warps x 16 rows).
// K smem [j][8] fp16, V smem [d][1024] fp16 (pitch 1032), Q smem [row][8] fp16
// pre-scaled by 1/sqrt(8)*log2(e). Streaming softmax: P = exp2(min(s-10, 15)).
// Bias cancels in l-division; clamp makes fp16 overflow impossible (2^15<65504)
// and activates only at s>25 (~6.3 exponential-tail units; ~0.2 elems expected).
// ---------------------------------------------------------------------------
#define VSP 1032

__global__ void __launch_bounds__(256) attn_kernel() {
    __shared__ __align__(16) __half ksm[1024 * 8];
    __shared__ __align__(16) __half vsm[8 * VSP];
    __shared__ __align__(16) __half qsm[128 * 8];

    int id = blockIdx.x;
    int tt = id & 31; id >>= 5;
    int h  = id & 7;  id >>= 3;
    int b  = id;
    int bh = b * 8 + h;
    int t0 = tt * 128;
    int tid = threadIdx.x;

    const float4* kg = (const float4*)&g_k16[(size_t)bh * (KP * DH)];
#pragma unroll
    for (int k = 0; k < 4; k++)
        ((float4*)ksm)[tid + k * 256] = kg[tid + k * 256];
    const float4* vg = (const float4*)&g_v16[(size_t)bh * (DH * KP)];
#pragma unroll
    for (int k = 0; k < 4; k++) {
        int i = tid + k * 256;             // 1024 float4 (=8 halves each)
        int d = i >> 7, c = i & 127;
        *(float4*)&vsm[d * VSP + c * 8] = vg[i];
    }
#pragma unroll
    for (int k = 0; k < 4; k++) {
        int i = tid + k * 256;             // 1024 elems
        int d = i >> 7, t = i & 127;
        float qv = g_qkv[(size_t)(b * J3 + d * 24 + h) * T_ + t0 + t];
        qsm[t * 8 + d] = __float2half_rn(qv * 0.51006973f);
    }
    __syncthreads();

    int w = tid >> 5, lane = tid & 31;
    int g = lane >> 2, tig = lane & 3;
    int wrow = w * 16;

    uint32_t qa0 = *(uint32_t*)&qsm[(wrow + g) * 8 + 2 * tig];
    uint32_t qa1 = *(uint32_t*)&qsm[(wrow + g + 8) * 8 + 2 * tig];

    float l0 = 0.f, l1 = 0.f;
    float o0 = 0.f, o1 = 0.f, o2 = 0.f, o3 = 0.f;

#pragma unroll 2
    for (int it = 0; it < 64; it++) {
        int j0 = it * 16;
        uint32_t kb0 = *(uint32_t*)&ksm[(j0 + g) * 8 + 2 * tig];
        uint32_t kb1 = *(uint32_t*)&ksm[(j0 + 8 + g) * 8 + 2 * tig];

        float s0 = 0.f, s1 = 0.f, s2 = 0.f, s3 = 0.f;
        asm volatile(
            "mma.sync.aligned.m16n8k8.row.col.f32.f16.f16.f32 "
            "{%0,%1,%2,%3}, {%4,%5}, {%6}, {%0,%1,%2,%3};"
            : "+f"(s0), "+f"(s1), "+f"(s2), "+f"(s3)
            : "r"(qa0), "r"(qa1), "r"(kb0));
        float u0 = 0.f, u1 = 0.f, u2 = 0.f, u3 = 0.f;
        asm volatile(
            "mma.sync.aligned.m16n8k8.row.col.f32.f16.f16.f32 "
            "{%0,%1,%2,%3}, {%4,%5}, {%6}, {%0,%1,%2,%3};"
            : "+f"(u0), "+f"(u1), "+f"(u2), "+f"(u3)
            : "r"(qa0), "r"(qa1), "r"(kb1));

        // P = exp2(min(s - 10, 15)) — fp16-overflow-proof, bias cancels in l-div
        s0 = fminf(s0 - 10.f, 15.f); s1 = fminf(s1 - 10.f, 15.f);
        s2 = fminf(s2 - 10.f, 15.f); s3 = fminf(s3 - 10.f, 15.f);
        u0 = fminf(u0 - 10.f, 15.f); u1 = fminf(u1 - 10.f, 15.f);
        u2 = fminf(u2 - 10.f, 15.f); u3 = fminf(u3 - 10.f, 15.f);
        asm("ex2.approx.f32 %0, %1;" : "=f"(s0) : "f"(s0));
        asm("ex2.approx.f32 %0, %1;" : "=f"(s1) : "f"(s1));
        asm("ex2.approx.f32 %0, %1;" : "=f"(s2) : "f"(s2));
        asm("ex2.approx.f32 %0, %1;" : "=f"(s3) : "f"(s3));
        asm("ex2.approx.f32 %0, %1;" : "=f"(u0) : "f"(u0));
        asm("ex2.approx.f32 %0, %1;" : "=f"(u1) : "f"(u1));
        asm("ex2.approx.f32 %0, %1;" : "=f"(u2) : "f"(u2));
        asm("ex2.approx.f32 %0, %1;" : "=f"(u3) : "f"(u3));

        l0 += s0 + s1 + u0 + u1;
        l1 += s2 + s3 + u2 + u3;

        __half2 pa0 = __floats2half2_rn(s0, s1);
        __half2 pa1 = __floats2half2_rn(s2, s3);
        __half2 pa2 = __floats2half2_rn(u0, u1);
        __half2 pa3 = __floats2half2_rn(u2, u3);

        uint32_t vb0 = *(uint32_t*)&vsm[g * VSP + j0 + 2 * tig];
        uint32_t vb1 = *(uint32_t*)&vsm[g * VSP + j0 + 2 * tig + 8];

        asm volatile(
            "mma.sync.aligned.m16n8k16.row.col.f32.f16.f16.f32 "
            "{%0,%1,%2,%3}, {%4,%5,%6,%7}, {%8,%9}, {%0,%1,%2,%3};"
            : "+f"(o0), "+f"(o1), "+f"(o2), "+f"(o3)
            : "r"(*(uint32_t*)&pa0), "r"(*(uint32_t*)&pa1),
              "r"(*(uint32_t*)&pa2), "r"(*(uint32_t*)&pa3),
              "r"(vb0), "r"(vb1));
    }

    // quad-reduce l over tig (lanes 4g..4g+3)
    l0 += __shfl_xor_sync(0xffffffffu, l0, 1);
    l0 += __shfl_xor_sync(0xffffffffu, l0, 2);
    l1 += __shfl_xor_sync(0xffffffffu, l1, 1);
    l1 += __shfl_xor_sync(0xffffffffu, l1, 2);

    float inv0 = __fdividef(1.f, l0);
    float inv1 = __fdividef(1.f, l1);
    o0 *= inv0; o1 *= inv0; o2 *= inv1; o3 *= inv1;

    int tr0 = t0 + wrow + g;
    int tr1 = tr0 + 8;
    size_t c0 = (size_t)(b * 64 + h * 8 + 2 * tig) * T_;
    g_att[c0 + tr0]      = o0;
    g_att[c0 + T_ + tr0] = o1;
    g_att[c0 + tr1]      = o2;
    g_att[c0 + T_ + tr1] = o3;
}

// ---------------------------------------------------------------------------
// out[b, c, t] = sum_cp g_att[b, cp, t] * W0[cp, c]
// ---------------------------------------------------------------------------
__global__ void outproj_kernel(const float* __restrict__ W0,
                               float* __restrict__ out) {
    __shared__ __align__(16) float w0s[64 * 64];
    __shared__ __align__(16) float as[64 * 64];
    int id = blockIdx.x;
    int tt = id & 63;
    int b  = id >> 6;
    int t0 = tt * 64;
    int tid = threadIdx.x;

#pragma unroll
    for (int k = 0; k < 4; k++) {
        int ii = tid + k * 256;
        int cp = ii >> 4, c4 = ii & 15;
        ((float4*)w0s)[ii] = *(const float4*)&W0[cp * 64 + c4 * 4];
    }
#pragma unroll
    for (int k = 0; k < 4; k++) {
        int ii = tid + k * 256;
        int cp = ii >> 4, t4 = ii & 15;
        ((float4*)as)[ii] = *(const float4*)&g_att[(b * 64 + cp) * T_ + t0 + t4 * 4];
    }
    __syncthreads();

    int tc = tid & 15, ti = tid >> 4;
    float acc[4][4];
#pragma unroll
    for (int a = 0; a < 4; a++)
#pragma unroll
        for (int u = 0; u < 4; u++) acc[a][u] = 0.f;
#pragma unroll
    for (int cp = 0; cp < 64; cp++) {
        float4 wv = *(float4*)&w0s[cp * 64 + tc * 4];
        float4 xv = *(float4*)&as[cp * 64 + ti * 4];
        float wa[4] = {wv.x, wv.y, wv.z, wv.w};
        float xa[4] = {xv.x, xv.y, xv.z, xv.w};
#pragma unroll
        for (int a = 0; a < 4; a++)
#pragma unroll
            for (int u = 0; u < 4; u++) acc[a][u] += wa[a] * xa[u];
    }
#pragma unroll
    for (int a = 0; a < 4; a++) {
        float4 o = make_float4(acc[a][0], acc[a][1], acc[a][2], acc[a][3]);
        *(float4*)&out[(b * 64 + tc * 4 + a) * T_ + t0 + ti * 4] = o;
    }
}

// ---------------------------------------------------------------------------
extern "C" void kernel_launch(void* const* d_in, const int* in_sizes, int n_in,
                              void* d_out, int out_size) {
    const float* x    = (const float*)d_in[0];
    const float* Wqkv = (const float*)d_in[5];
    const float* W0   = (const float*)d_in[6];
    const float* E    = (const float*)d_in[7];
    float* out = (float*)d_out;

    const int proj_smem = 3 * PJ_STAGE;                    // 82944 B
    cudaFuncSetAttribute(proj_mma_kernel, cudaFuncAttributeMaxDynamicSharedMemorySize, proj_smem);

    zero_kv_kernel<<<512, 256>>>();
    qkv_kernel<<<B_ * 3 * (T_ / 64), 256>>>(x, Wqkv);
    transpose_E<<<dim3(KP / 32, T_ / 32), 256>>>(E);
    proj_mma_kernel<<<128, 128, proj_smem>>>();
    kv16_kernel<<<32, 256>>>();
    attn_kernel<<<B_ * NH * (T_ / 128), 256>>>();
    outproj_kernel<<<B_ * (T_ / 64), 256>>>(W0, out);
}